// round 3
// baseline (speedup 1.0000x reference)
#include <cuda_runtime.h>
#include <cstdint>

#define NN   50000
#define NPAD 50048          // 782 * 64
#define EE   1000000
#define RR   16
#define DD   128
#define GG   64
#define LL   3
#define CTOT 2176           // (R+1)*D : 16 relation blocks + root block
#define KD   128

// ---------------- static device scratch (no allocation allowed) ----------------
__device__ float    g_x[(size_t)NPAD * DD];      // current node features
__device__ float    g_Y[(size_t)NPAD * CTOT];    // transformed features per relation (+root)
__device__ float    g_W[KD * CTOT];              // fused weight [i][r*128+o | root]
__device__ float    g_invc[NN * RR];
__device__ int      g_cnt[NN * RR];
__device__ int      g_deg[NN];
__device__ int      g_cur[NN];
__device__ int      g_off[NN + 1];
__device__ unsigned g_adj[EE];                   // src | (type<<16), grouped by dst
__device__ float    g_gcnt[GG];

// ---------------- helpers ----------------
__device__ __forceinline__ unsigned f2tf(float f) {
    unsigned u;
    asm("cvt.rna.tf32.f32 %0, %1;" : "=r"(u) : "f"(f));
    return u;
}

__device__ __forceinline__ void mma_tf32(float* c, const unsigned* a, const unsigned* b) {
    asm volatile(
        "mma.sync.aligned.m16n8k8.row.col.f32.tf32.tf32.f32 "
        "{%0,%1,%2,%3}, {%4,%5,%6,%7}, {%8,%9}, {%0,%1,%2,%3};"
        : "+f"(c[0]), "+f"(c[1]), "+f"(c[2]), "+f"(c[3])
        : "r"(a[0]), "r"(a[1]), "r"(a[2]), "r"(a[3]), "r"(b[0]), "r"(b[1]));
}

// ---------------- preprocessing ----------------
__global__ void k_zero() {
    int i = blockIdx.x * 256 + threadIdx.x;
    if (i < NN * RR) g_cnt[i] = 0;
    if (i < NN) { g_deg[i] = 0; g_cur[i] = 0; }
    if (i < GG) g_gcnt[i] = 0.0f;
}

__global__ void k_count(const int* __restrict__ ei, const int* __restrict__ et) {
    int e = blockIdx.x * 256 + threadIdx.x;
    if (e >= EE) return;
    int dst = ei[EE + e];
    int t   = et[e];
    atomicAdd(&g_cnt[dst * RR + t], 1);
    atomicAdd(&g_deg[dst], 1);
}

__global__ void k_scan() {   // single block, 1024 threads, 49 items/thread
    __shared__ int sh[1024];
    const int IT = 49;
    int t = threadIdx.x;
    int base = t * IT;
    int s = 0;
    for (int j = 0; j < IT; j++) { int i = base + j; if (i < NN) s += g_deg[i]; }
    sh[t] = s;
    __syncthreads();
    for (int d = 1; d < 1024; d <<= 1) {
        int v = (t >= d) ? sh[t - d] : 0;
        __syncthreads();
        sh[t] += v;
        __syncthreads();
    }
    int run = sh[t] - s;   // exclusive
    for (int j = 0; j < IT; j++) {
        int i = base + j;
        if (i < NN) { g_off[i] = run; run += g_deg[i]; }
    }
    if (t == 1023) g_off[NN] = sh[1023];
}

__global__ void k_fill(const int* __restrict__ ei, const int* __restrict__ et) {
    int e = blockIdx.x * 256 + threadIdx.x;
    if (e >= EE) return;
    int src = ei[e];
    int dst = ei[EE + e];
    int t   = et[e];
    int p = atomicAdd(&g_cur[dst], 1);
    g_adj[g_off[dst] + p] = (unsigned)src | ((unsigned)t << 16);
}

__global__ void k_invc() {
    int i = blockIdx.x * 256 + threadIdx.x;
    if (i >= NN * RR) return;
    int c = g_cnt[i];
    g_invc[i] = 1.0f / (float)(c > 1 ? c : 1);
}

__global__ void k_gather(const int* __restrict__ node_ids, const float* __restrict__ emb,
                         const int* __restrict__ batch) {
    int tid = blockIdx.x * 256 + threadIdx.x;
    int n = tid >> 5, l = tid & 31;
    if (n >= NN) return;
    int nid = node_ids[n];
    ((float4*)g_x)[(size_t)n * 32 + l] = ((const float4*)emb)[(size_t)nid * 32 + l];
    if (l == 0) atomicAdd(&g_gcnt[batch[n]], 1.0f);
}

// ---------------- per-layer ----------------
__global__ void k_wbuild(const float* __restrict__ comp_l, const float* __restrict__ basis_l,
                         const float* __restrict__ root_l) {
    int idx = blockIdx.x * 256 + threadIdx.x;
    if (idx >= KD * CTOT) return;
    int i = idx / CTOT;
    int c = idx - i * CTOT;
    float acc;
    if (c < RR * DD) {
        int r = c >> 7, o = c & 127;
        acc = 0.0f;
#pragma unroll
        for (int b = 0; b < 16; b++)
            acc += comp_l[r * 16 + b] * basis_l[((size_t)b * 128 + i) * 128 + o];
    } else {
        acc = root_l[i * 128 + (c - 2048)];
    }
    g_W[idx] = acc;
}

// GEMM: Y[NPAD x 2176] = X[NPAD x 128] @ W[128 x 2176], tf32 tensor cores.
// Block: 64 rows, 4 warps (2x2), each warp 32x32, columns chunked by 64 (34 chunks).
__global__ void __launch_bounds__(128) k_gemm() {
    extern __shared__ unsigned sm[];
    unsigned* As = sm;              // [64][132] tf32 bits
    unsigned* Bs = sm + 64 * 132;   // [128][72] tf32 bits
    int tid = threadIdx.x, warp = tid >> 5, lane = tid & 31;
    int wm = warp >> 1, wn = warp & 1;
    int g = lane >> 2, tg = lane & 3;
    size_t mBase = (size_t)blockIdx.x * 64;

    for (int j = tid; j < 64 * 32; j += 128) {
        int m = j >> 5, k4 = (j & 31) * 4;
        float4 v = *(const float4*)&g_x[(mBase + m) * KD + k4];
        unsigned* d = &As[m * 132 + k4];
        d[0] = f2tf(v.x); d[1] = f2tf(v.y); d[2] = f2tf(v.z); d[3] = f2tf(v.w);
    }
    __syncthreads();

    for (int cb = 0; cb < CTOT; cb += 64) {
        for (int j = tid; j < 128 * 16; j += 128) {
            int k = j >> 4, n4 = (j & 15) * 4;
            float4 v = *(const float4*)&g_W[k * CTOT + cb + n4];
            unsigned* d = &Bs[k * 72 + n4];
            d[0] = f2tf(v.x); d[1] = f2tf(v.y); d[2] = f2tf(v.z); d[3] = f2tf(v.w);
        }
        __syncthreads();

        float c[2][4][4];
#pragma unroll
        for (int mt = 0; mt < 2; mt++)
#pragma unroll
            for (int nt = 0; nt < 4; nt++)
#pragma unroll
                for (int q = 0; q < 4; q++) c[mt][nt][q] = 0.0f;

#pragma unroll
        for (int ks = 0; ks < 16; ks++) {
            int k0 = ks * 8;
            unsigned a[2][4], b[4][2];
#pragma unroll
            for (int mt = 0; mt < 2; mt++) {
                int r0 = wm * 32 + mt * 16 + g;
                a[mt][0] = As[r0 * 132 + k0 + tg];
                a[mt][1] = As[(r0 + 8) * 132 + k0 + tg];
                a[mt][2] = As[r0 * 132 + k0 + tg + 4];
                a[mt][3] = As[(r0 + 8) * 132 + k0 + tg + 4];
            }
#pragma unroll
            for (int nt = 0; nt < 4; nt++) {
                int nc = wn * 32 + nt * 8 + g;
                b[nt][0] = Bs[(k0 + tg) * 72 + nc];
                b[nt][1] = Bs[(k0 + tg + 4) * 72 + nc];
            }
#pragma unroll
            for (int mt = 0; mt < 2; mt++)
#pragma unroll
                for (int nt = 0; nt < 4; nt++)
                    mma_tf32(c[mt][nt], a[mt], b[nt]);
        }
        __syncthreads();

#pragma unroll
        for (int mt = 0; mt < 2; mt++)
#pragma unroll
            for (int nt = 0; nt < 4; nt++) {
                size_t row = mBase + wm * 32 + mt * 16 + g;
                int col = cb + wn * 32 + nt * 8 + tg * 2;
                *(float2*)&g_Y[row * CTOT + col]       = make_float2(c[mt][nt][0], c[mt][nt][1]);
                *(float2*)&g_Y[(row + 8) * CTOT + col] = make_float2(c[mt][nt][2], c[mt][nt][3]);
            }
    }
}

// Aggregation + bias + layernorm + relu + residual. One warp per destination node.
__global__ void __launch_bounds__(256) k_agg(const float* __restrict__ gam,
                                             const float* __restrict__ bet,
                                             const float* __restrict__ bias_l,
                                             int last, float* __restrict__ out) {
    int n = blockIdx.x * 8 + (threadIdx.x >> 5);
    int lane = threadIdx.x & 31;
    if (n >= NN) return;

    const float4* Y4 = (const float4*)g_Y;
    float4 acc = Y4[(size_t)n * 544 + 512 + lane];       // root term X@root
    float4 bb = ((const float4*)bias_l)[lane];
    acc.x += bb.x; acc.y += bb.y; acc.z += bb.z; acc.w += bb.w;

    int beg = g_off[n], end = g_off[n + 1];
#pragma unroll 4
    for (int e = beg; e < end; e++) {
        unsigned p = g_adj[e];
        int src = p & 0xffff;
        int r   = p >> 16;
        float w = g_invc[n * RR + r];
        float4 v = Y4[(size_t)src * 544 + r * 32 + lane];
        acc.x += w * v.x; acc.y += w * v.y; acc.z += w * v.z; acc.w += w * v.w;
    }

    float s  = acc.x + acc.y + acc.z + acc.w;
    float s2 = acc.x * acc.x + acc.y * acc.y + acc.z * acc.z + acc.w * acc.w;
#pragma unroll
    for (int o = 16; o; o >>= 1) {
        s  += __shfl_xor_sync(0xffffffffu, s, o);
        s2 += __shfl_xor_sync(0xffffffffu, s2, o);
    }
    float mu  = s * (1.0f / 128.0f);
    float var = s2 * (1.0f / 128.0f) - mu * mu;
    float rs  = rsqrtf(var + 1e-5f);

    float4 gm = ((const float4*)gam)[lane];
    float4 bt = ((const float4*)bet)[lane];
    float4 xi = ((const float4*)g_x)[(size_t)n * 32 + lane];
    float4 o4;
    o4.x = xi.x + fmaxf((acc.x - mu) * rs * gm.x + bt.x, 0.0f);
    o4.y = xi.y + fmaxf((acc.y - mu) * rs * gm.y + bt.y, 0.0f);
    o4.z = xi.z + fmaxf((acc.z - mu) * rs * gm.z + bt.z, 0.0f);
    o4.w = xi.w + fmaxf((acc.w - mu) * rs * gm.w + bt.w, 0.0f);

    float4* dst = last ? (float4*)out : (float4*)g_x;
    dst[(size_t)n * 32 + lane] = o4;
}

// ---------------- pooling ----------------
__global__ void k_pool(const int* __restrict__ batch, float* __restrict__ out) {
    int tid = blockIdx.x * 256 + threadIdx.x;
    int n = tid >> 5, l = tid & 31;
    if (n >= NN) return;
    int gid = batch[n];
    float4 v = ((const float4*)out)[(size_t)n * 32 + l];
    float* p = out + (size_t)NN * DD + gid * DD + l * 4;
    atomicAdd(p + 0, v.x);
    atomicAdd(p + 1, v.y);
    atomicAdd(p + 2, v.z);
    atomicAdd(p + 3, v.w);
}

__global__ void k_norm(float* __restrict__ out) {
    int i = blockIdx.x * 256 + threadIdx.x;
    if (i >= GG * DD) return;
    float c = g_gcnt[i >> 7];
    out[(size_t)NN * DD + i] *= 1.0f / fmaxf(c, 1.0f);
}

// ---------------- launch ----------------
extern "C" void kernel_launch(void* const* d_in, const int* in_sizes, int n_in,
                              void* d_out, int out_size) {
    const int*   node_ids = (const int*)d_in[0];
    const int*   ei       = (const int*)d_in[1];
    const int*   et       = (const int*)d_in[2];
    const int*   batch    = (const int*)d_in[3];
    const float* emb      = (const float*)d_in[4];
    const float* comp     = (const float*)d_in[5];
    const float* basis    = (const float*)d_in[6];
    const float* root     = (const float*)d_in[7];
    const float* bias     = (const float*)d_in[8];
    const float* gam      = (const float*)d_in[9];
    const float* bet      = (const float*)d_in[10];
    float* out = (float*)d_out;

    cudaFuncSetAttribute(k_gemm, cudaFuncAttributeMaxDynamicSharedMemorySize, 70656);

    k_zero<<<(NN * RR + 255) / 256, 256>>>();
    k_count<<<(EE + 255) / 256, 256>>>(ei, et);
    k_scan<<<1, 1024>>>();
    k_fill<<<(EE + 255) / 256, 256>>>(ei, et);
    k_invc<<<(NN * RR + 255) / 256, 256>>>();
    k_gather<<<(NN * 32 + 255) / 256, 256>>>(node_ids, emb, batch);

    for (int l = 0; l < LL; l++) {
        k_wbuild<<<(KD * CTOT + 255) / 256, 256>>>(comp + l * RR * 16,
                                                   basis + (size_t)l * 16 * 128 * 128,
                                                   root + (size_t)l * 128 * 128);
        k_gemm<<<NPAD / 64, 128, 70656>>>();
        k_agg<<<(NN + 7) / 8, 256>>>(gam + l * 128, bet + l * 128, bias + l * 128,
                                     (l == LL - 1) ? 1 : 0, out);
    }

    cudaMemsetAsync(out + (size_t)NN * DD, 0, (size_t)GG * DD * sizeof(float));
    k_pool<<<(NN * 32 + 255) / 256, 256>>>(batch, out);
    k_norm<<<(GG * DD + 255) / 256, 256>>>(out);
}